// round 9
// baseline (speedup 1.0000x reference)
#include <cuda_runtime.h>
#include <cuda_bf16.h>
#include <math.h>

#define H 512
#define W 512
#define BATCH 16
#define NPIX (H*W)
#define CA 0.955f
#define CB 1.3693f
#define CINF 1e6f
#define BIG 1e30f

#define LBLK 256
#define BPI 16
#define NLB (BATCH*BPI)

// ---------------- device scratch ----------------
__device__ float    g_dist[BATCH*NPIX];
__device__ float    g_mx[BATCH];
__device__ int      g_flags[BATCH];
__device__ float    g_part[NLB*5];
__device__ unsigned g_seed[BATCH*H*16];   // 512 KB seed bitmaps

// =============== seed kernel: bitmap + dilate/erode -> seed bits ===============
__global__ __launch_bounds__(128) void seed_kernel(const int* __restrict__ target) {
    __shared__ unsigned mbits[H * 18];
    __shared__ int sflag[2];

    const int img = blockIdx.x;
    const int* tg = target + img * NPIX;
    unsigned* sb = g_seed + img * H * 16;

    const int tid  = threadIdx.x;
    const int lane = tid & 31;
    const int sl   = tid & 7;
    const int sg   = tid >> 3;
    const int col0 = tid * 4;
    const unsigned FM = 0xffffffffu;

    if (tid < 2) sflag[tid] = 0;
    for (int r = tid; r < H; r += 128) {
        mbits[r * 18 + 0]  = 0u;
        mbits[r * 18 + 17] = 0u;
    }
    __syncthreads();

    bool any1 = false, any0 = false;
    for (int r = 0; r < H; r++) {
        int4 tv = *(const int4*)(tg + r * W + col0);
        unsigned nib = (unsigned)(tv.x != 0) | ((unsigned)(tv.y != 0) << 1)
                     | ((unsigned)(tv.z != 0) << 2) | ((unsigned)(tv.w != 0) << 3);
        any1 |= (nib != 0u);
        any0 |= (nib != 15u);
        unsigned word = nib << (4 * sl);
        word |= __shfl_xor_sync(FM, word, 1);
        word |= __shfl_xor_sync(FM, word, 2);
        word |= __shfl_xor_sync(FM, word, 4);
        if (sl == 0) mbits[r * 18 + 1 + sg] = word;
    }
    if (__any_sync(FM, any1) && lane == 0) atomicOr(&sflag[0], 1);
    if (__any_sync(FM, any0) && lane == 0) atomicOr(&sflag[1], 1);
    __syncthreads();
    const int hasb = sflag[0] & sflag[1];

    for (int idx = tid; idx < H * 16; idx += 128) {
        int r = idx >> 4, w = idx & 15;
        unsigned swd;
        if (hasb) {
            unsigned dil = 0u, ero = 0xffffffffu;
            #pragma unroll
            for (int dr = -1; dr <= 1; dr++) {
                int r2 = r + dr;
                if (r2 < 0 || r2 >= H) continue;
                unsigned M  = mbits[r2 * 18 + 1 + w];
                unsigned Ml = mbits[r2 * 18 + w];
                unsigned Mr = mbits[r2 * 18 + 2 + w];
                unsigned Mlg = (w == 0)  ? 0xffffffffu : Ml;
                unsigned Mrg = (w == 15) ? 0xffffffffu : Mr;
                dil |= M | __funnelshift_l(Ml, M, 1) | __funnelshift_r(M, Mr, 1);
                ero &= M & __funnelshift_l(Mlg, M, 1) & __funnelshift_r(M, Mrg, 1);
            }
            swd = dil & ~ero;
        } else {
            swd = ~mbits[r * 18 + 1 + w];
        }
        sb[idx] = swd;
    }
    if (tid == 0) g_flags[img] = sflag[0] | (sflag[1] << 1);
}

// ---------------- warp-scan helpers (bit-exact, from passing R5 kernel) ----------------
__device__ __forceinline__ float scan_up(float x, int t) {
    const unsigned FM = 0xffffffffu;
    float o;
    o = __shfl_up_sync(FM, x, 1);  if (t >= 1)  x = fminf(x, o);
    o = __shfl_up_sync(FM, x, 2);  if (t >= 2)  x = fminf(x, o);
    o = __shfl_up_sync(FM, x, 4);  if (t >= 4)  x = fminf(x, o);
    o = __shfl_up_sync(FM, x, 8);  if (t >= 8)  x = fminf(x, o);
    o = __shfl_up_sync(FM, x, 16); if (t >= 16) x = fminf(x, o);
    return x;
}
__device__ __forceinline__ float scan_dn(float x, int t) {
    const unsigned FM = 0xffffffffu;
    float o;
    o = __shfl_down_sync(FM, x, 1);  if (t <= 30) x = fminf(x, o);
    o = __shfl_down_sync(FM, x, 2);  if (t <= 29) x = fminf(x, o);
    o = __shfl_down_sync(FM, x, 4);  if (t <= 27) x = fminf(x, o);
    o = __shfl_down_sync(FM, x, 8);  if (t <= 23) x = fminf(x, o);
    o = __shfl_down_sync(FM, x, 16); if (t <= 15) x = fminf(x, o);
    return x;
}

// forward m+v computation (v = m - aj, via +naj; all fmins exact)
__device__ __forceinline__ void fwd_mv(const float* p, float pvL, float pvR,
                                       unsigned hw, const float* naj, float* v) {
    #pragma unroll
    for (int c = 0; c < 16; c++) {
        float pl = (c == 0)  ? pvL : p[c - 1];
        float pr = (c == 15) ? pvR : p[c + 1];
        float dv = ((hw >> c) & 1u) ? 0.0f : CINF;
        float t1 = p[c] + CA;
        float t3 = fminf(pl, pr) + CB;
        float m  = fminf(fminf(t1, t3), dv);
        v[c] = m + naj[c];
    }
}
// backward m+v (drw instead of seed)
__device__ __forceinline__ void bwd_mv(const float* p, float pvL, float pvR,
                                       const float* drw, const float* nar, float* v) {
    #pragma unroll
    for (int c = 0; c < 16; c++) {
        float pl = (c == 0)  ? pvL : p[c - 1];
        float pr = (c == 15) ? pvR : p[c + 1];
        float t1 = p[c] + CA;
        float t3 = fminf(pl, pr) + CB;
        float m  = fminf(fminf(t1, t3), drw[c]);
        v[c] = m + nar[c];
    }
}

// =============== dt kernel: ONE WARP handles TWO images (fills scan bubbles) ===============
__global__ __launch_bounds__(32) void dt_warp2_kernel() {
    const int pair = blockIdx.x;              // 0..7
    const int imgA = 2 * pair, imgB = 2 * pair + 1;
    const unsigned* sbA = g_seed + imgA * H * 16;
    const unsigned* sbB = g_seed + imgB * H * 16;
    float* ddA = g_dist + imgA * NPIX;
    float* ddB = g_dist + imgB * NPIX;

    const int t  = threadIdx.x;
    const int c0 = t * 16;
    const unsigned FM = 0xffffffffu;
    const int wsel = t >> 1;
    const int wsh  = (t & 1) * 16;

    float aj[16], naj[16];
    #pragma unroll
    for (int c = 0; c < 16; c++) { aj[c] = CA * (float)(c0 + c); naj[c] = -aj[c]; }
    const float ajL = CA * (float)(c0 - 1);
    const float ajR = CA * (float)(c0 + 16);

    // ================= forward pass (both images) =================
    float pA[16], pB[16];
    #pragma unroll
    for (int c = 0; c < 16; c++) { pA[c] = CINF; pB[c] = CINF; }
    float pvLA = CINF, pvRA = CINF, pvLB = CINF, pvRB = CINF;

    unsigned hwA = (sbA[wsel] >> wsh) & 0xffffu;
    unsigned hwB = (sbB[wsel] >> wsh) & 0xffffu;

    for (int i = 0; i < H; i++) {
        unsigned hnA = 0u, hnB = 0u;
        if (i < H - 1) {
            hnA = (sbA[(i + 1) * 16 + wsel] >> wsh) & 0xffffu;
            hnB = (sbB[(i + 1) * 16 + wsel] >> wsh) & 0xffffu;
        }

        float vA[16], vB[16];
        fwd_mv(pA, pvLA, pvRA, hwA, naj, vA);
        fwd_mv(pB, pvLB, pvRB, hwB, naj, vB);
        float vR0A = __shfl_down_sync(FM, vA[0], 1);
        float vR0B = __shfl_down_sync(FM, vB[0], 1);

        #pragma unroll
        for (int c = 1; c < 16; c++) vA[c] = fminf(vA[c - 1], vA[c]);
        #pragma unroll
        for (int c = 1; c < 16; c++) vB[c] = fminf(vB[c - 1], vB[c]);

        float sAv = scan_up(vA[15], t);
        float sBv = scan_up(vB[15], t);
        float exA = __shfl_up_sync(FM, sAv, 1); if (t == 0) exA = BIG;
        float exB = __shfl_up_sync(FM, sBv, 1); if (t == 0) exB = BIG;

        #pragma unroll
        for (int c = 0; c < 16; c++) pA[c] = aj[c] + fminf(exA, vA[c]);
        #pragma unroll
        for (int c = 0; c < 16; c++) pB[c] = aj[c] + fminf(exB, vB[c]);

        float* rowA = ddA + i * W + c0;
        *(float4*)(rowA + 0)  = make_float4(pA[0],  pA[1],  pA[2],  pA[3]);
        *(float4*)(rowA + 4)  = make_float4(pA[4],  pA[5],  pA[6],  pA[7]);
        *(float4*)(rowA + 8)  = make_float4(pA[8],  pA[9],  pA[10], pA[11]);
        *(float4*)(rowA + 12) = make_float4(pA[12], pA[13], pA[14], pA[15]);
        float* rowB = ddB + i * W + c0;
        *(float4*)(rowB + 0)  = make_float4(pB[0],  pB[1],  pB[2],  pB[3]);
        *(float4*)(rowB + 4)  = make_float4(pB[4],  pB[5],  pB[6],  pB[7]);
        *(float4*)(rowB + 8)  = make_float4(pB[8],  pB[9],  pB[10], pB[11]);
        *(float4*)(rowB + 12) = make_float4(pB[12], pB[13], pB[14], pB[15]);

        pvLA = (t == 0)  ? CINF : (ajL + exA);
        pvRA = (t == 31) ? CINF : (ajR + fminf(sAv, vR0A));
        pvLB = (t == 0)  ? CINF : (ajL + exB);
        pvRB = (t == 31) ? CINF : (ajR + fminf(sBv, vR0B));
        hwA = hnA; hwB = hnB;
    }

    // ================= backward pass (both images) =================
    float ar[16], nar[16];
    #pragma unroll
    for (int c = 0; c < 16; c++) { ar[c] = CA * (float)(W - 1 - (c0 + c)); nar[c] = -ar[c]; }
    const float arL = CA * (float)(W - c0);
    const float arR = CA * (float)(W - 17 - c0);

    #pragma unroll
    for (int c = 0; c < 16; c++) { pA[c] = CINF; pB[c] = CINF; }
    pvLA = CINF; pvRA = CINF; pvLB = CINF; pvRB = CINF;
    float lmA = 0.0f, lmB = 0.0f;

    float4 a0, a1, a2, a3, b0, b1, b2, b3;
    {
        const float* rA = ddA + (H - 1) * W + c0;
        a0 = *(const float4*)(rA + 0); a1 = *(const float4*)(rA + 4);
        a2 = *(const float4*)(rA + 8); a3 = *(const float4*)(rA + 12);
        const float* rB = ddB + (H - 1) * W + c0;
        b0 = *(const float4*)(rB + 0); b1 = *(const float4*)(rB + 4);
        b2 = *(const float4*)(rB + 8); b3 = *(const float4*)(rB + 12);
    }

    for (int i = H - 1; i >= 0; i--) {
        float drA[16] = {a0.x,a0.y,a0.z,a0.w, a1.x,a1.y,a1.z,a1.w,
                         a2.x,a2.y,a2.z,a2.w, a3.x,a3.y,a3.z,a3.w};
        float drB[16] = {b0.x,b0.y,b0.z,b0.w, b1.x,b1.y,b1.z,b1.w,
                         b2.x,b2.y,b2.z,b2.w, b3.x,b3.y,b3.z,b3.w};
        if (i > 0) {
            const float* rA = ddA + (i - 1) * W + c0;
            a0 = *(const float4*)(rA + 0); a1 = *(const float4*)(rA + 4);
            a2 = *(const float4*)(rA + 8); a3 = *(const float4*)(rA + 12);
            const float* rB = ddB + (i - 1) * W + c0;
            b0 = *(const float4*)(rB + 0); b1 = *(const float4*)(rB + 4);
            b2 = *(const float4*)(rB + 8); b3 = *(const float4*)(rB + 12);
        }

        float vA[16], vB[16];
        bwd_mv(pA, pvLA, pvRA, drA, nar, vA);
        bwd_mv(pB, pvLB, pvRB, drB, nar, vB);
        float vL15A = __shfl_up_sync(FM, vA[15], 1);
        float vL15B = __shfl_up_sync(FM, vB[15], 1);

        #pragma unroll
        for (int c = 14; c >= 0; c--) vA[c] = fminf(vA[c], vA[c + 1]);
        #pragma unroll
        for (int c = 14; c >= 0; c--) vB[c] = fminf(vB[c], vB[c + 1]);

        float sAv = scan_dn(vA[0], t);
        float sBv = scan_dn(vB[0], t);
        float exA = __shfl_down_sync(FM, sAv, 1); if (t == 31) exA = BIG;
        float exB = __shfl_down_sync(FM, sBv, 1); if (t == 31) exB = BIG;

        #pragma unroll
        for (int c = 0; c < 16; c++) { pA[c] = ar[c] + fminf(exA, vA[c]); lmA = fmaxf(lmA, pA[c]); }
        #pragma unroll
        for (int c = 0; c < 16; c++) { pB[c] = ar[c] + fminf(exB, vB[c]); lmB = fmaxf(lmB, pB[c]); }

        float* rowA = ddA + i * W + c0;
        *(float4*)(rowA + 0)  = make_float4(pA[0],  pA[1],  pA[2],  pA[3]);
        *(float4*)(rowA + 4)  = make_float4(pA[4],  pA[5],  pA[6],  pA[7]);
        *(float4*)(rowA + 8)  = make_float4(pA[8],  pA[9],  pA[10], pA[11]);
        *(float4*)(rowA + 12) = make_float4(pA[12], pA[13], pA[14], pA[15]);
        float* rowB = ddB + i * W + c0;
        *(float4*)(rowB + 0)  = make_float4(pB[0],  pB[1],  pB[2],  pB[3]);
        *(float4*)(rowB + 4)  = make_float4(pB[4],  pB[5],  pB[6],  pB[7]);
        *(float4*)(rowB + 8)  = make_float4(pB[8],  pB[9],  pB[10], pB[11]);
        *(float4*)(rowB + 12) = make_float4(pB[12], pB[13], pB[14], pB[15]);

        pvRA = (t == 31) ? CINF : (arR + exA);
        pvLA = (t == 0)  ? CINF : (arL + fminf(sAv, vL15A));
        pvRB = (t == 31) ? CINF : (arR + exB);
        pvLB = (t == 0)  ? CINF : (arL + fminf(sBv, vL15B));
    }

    // per-image max
    #pragma unroll
    for (int d = 16; d > 0; d >>= 1) {
        lmA = fmaxf(lmA, __shfl_xor_sync(FM, lmA, d));
        lmB = fmaxf(lmB, __shfl_xor_sync(FM, lmB, d));
    }
    if (t == 0) { g_mx[imgA] = lmA; g_mx[imgB] = lmB; }
}

// ---------------- loss partial sums ----------------
__global__ __launch_bounds__(LBLK) void loss_partial(const float* __restrict__ pred,
                                                     const int* __restrict__ target) {
    const int img = blockIdx.x / BPI;
    const int sub = blockIdx.x % BPI;
    const int base = img * NPIX;
    const float mx = g_mx[img];
    const int hfg = g_flags[img] & 1;
    const float inv = 1.0f / fmaxf(mx, 1e-12f);
    const int usediv = (mx > 0.0f) ? 1 : 0;

    float sF = 0.f, sB = 0.f, sP = 0.f, sT = 0.f, sPT = 0.f;
    for (int idx = sub * LBLK + threadIdx.x; idx < NPIX; idx += BPI * LBLK) {
        float x = pred[base + idx];
        int tv = target[base + idx];
        float d = g_dist[base + idx];
        float p = 1.0f / (1.0f + expf(-x));
        float ax = fabsf(x);
        float bce = log1pf(expf(-ax)) + (tv ? fmaxf(-x, 0.0f) : fmaxf(x, 0.0f));
        float pt = tv ? p : (1.0f - p);
        float omp = 1.0f - pt;
        float alpha = tv ? 0.25f : 0.75f;
        sF += alpha * omp * omp * bce;
        float dn = hfg ? (usediv ? d * inv : d) : 1.0f;
        sB += omp * (1.0f + dn);
        sP += p;
        if (tv) { sT += 1.0f; sPT += p; }
    }

    float vals[5] = {sF, sB, sP, sT, sPT};
    #pragma unroll
    for (int k = 0; k < 5; k++) {
        float v = vals[k];
        #pragma unroll
        for (int d = 16; d > 0; d >>= 1) v += __shfl_xor_sync(0xffffffffu, v, d);
        vals[k] = v;
    }
    __shared__ float s5[LBLK / 32][5];
    int lane = threadIdx.x & 31, wid = threadIdx.x >> 5;
    if (lane == 0) {
        #pragma unroll
        for (int k = 0; k < 5; k++) s5[wid][k] = vals[k];
    }
    __syncthreads();
    if (threadIdx.x == 0) {
        #pragma unroll
        for (int k = 0; k < 5; k++) {
            float a = 0.f;
            for (int w = 0; w < LBLK / 32; w++) a += s5[w][k];
            g_part[blockIdx.x * 5 + k] = a;
        }
    }
}

// ---------------- final combine ----------------
__global__ void loss_final(const float* __restrict__ lv, float* __restrict__ out,
                           int out_size) {
    __shared__ double sd[BATCH][4];
    int t = threadIdx.x;
    if (t < BATCH) {
        double F = 0, Bd = 0, P = 0, T = 0, PT = 0;
        for (int b = 0; b < BPI; b++) {
            const float* pp = g_part + (t * BPI + b) * 5;
            F += pp[0]; Bd += pp[1]; P += pp[2]; T += pp[3]; PT += pp[4];
        }
        double total = P + T;
        double uni = total - PT;
        sd[t][0] = F;
        sd[t][1] = Bd;
        sd[t][2] = (2.0 * PT + 1e-6) / (total + 1e-6);
        sd[t][3] = (PT + 1e-6) / (uni + 1e-6);
    }
    __syncthreads();
    if (t == 0) {
        double F = 0, Bd = 0, D = 0, I = 0;
        for (int b = 0; b < BATCH; b++) {
            F += sd[b][0]; Bd += sd[b][1]; D += sd[b][2]; I += sd[b][3];
        }
        double N = (double)BATCH * (double)NPIX;
        double focal = F / N;
        double bnd   = Bd / N;
        double dice  = 1.0 - D / (double)BATCH;
        double iou   = 1.0 - I / (double)BATCH;
        double l0 = (double)lv[0], l1 = (double)lv[1], l2 = (double)lv[2], l3 = (double)lv[3];
        double tot = exp(-l0) * focal + l0
                   + exp(-l1) * dice  + l1
                   + exp(-l2) * bnd   + l2
                   + exp(-l3) * iou   + l3;
        if (out_size > 0) out[0] = (float)tot;
        if (out_size > 1) out[1] = (float)focal;
        if (out_size > 2) out[2] = (float)dice;
        if (out_size > 3) out[3] = (float)bnd;
        if (out_size > 4) out[4] = (float)iou;
    }
}

extern "C" void kernel_launch(void* const* d_in, const int* in_sizes, int n_in,
                              void* d_out, int out_size) {
    const float* pred   = (const float*)d_in[0];
    const int*   target = (const int*)d_in[1];
    const float* lv     = (const float*)d_in[2];
    float* out = (float*)d_out;

    seed_kernel<<<BATCH, 128>>>(target);
    dt_warp2_kernel<<<BATCH / 2, 32>>>();
    loss_partial<<<NLB, LBLK>>>(pred, target);
    loss_final<<<1, 32>>>(lv, out, out_size);
}

// round 11
// speedup vs baseline: 2.5701x; 2.5701x over previous
#include <cuda_runtime.h>
#include <math.h>

#define H 512
#define W 512
#define BATCH 16
#define NPIX (H*W)
#define CA 0.955f
#define CB 1.3693f
#define CINF 1e6f
#define BIG 1e30f
#define NG 64
#define LBLK 256
#define BPI 16
#define NLB (BATCH*BPI)

__device__ float    g_dist[BATCH*NPIX];
__device__ int      g_mxi[BATCH];
__device__ int      g_flags[BATCH];
__device__ float    g_part[NLB*5];
__device__ unsigned g_seed[BATCH*H*16];
__device__ float    g_L[BATCH*NG*W];

__device__ __forceinline__ void ld16(const float* b, float* a) {
    float4 x0 = *(const float4*)(b + 0), x1 = *(const float4*)(b + 4);
    float4 x2 = *(const float4*)(b + 8), x3 = *(const float4*)(b + 12);
    a[0]=x0.x;a[1]=x0.y;a[2]=x0.z;a[3]=x0.w; a[4]=x1.x;a[5]=x1.y;a[6]=x1.z;a[7]=x1.w;
    a[8]=x2.x;a[9]=x2.y;a[10]=x2.z;a[11]=x2.w; a[12]=x3.x;a[13]=x3.y;a[14]=x3.z;a[15]=x3.w;
}
__device__ __forceinline__ void st16(float* b, const float* a) {
    *(float4*)(b+0)  = make_float4(a[0],a[1],a[2],a[3]);
    *(float4*)(b+4)  = make_float4(a[4],a[5],a[6],a[7]);
    *(float4*)(b+8)  = make_float4(a[8],a[9],a[10],a[11]);
    *(float4*)(b+12) = make_float4(a[12],a[13],a[14],a[15]);
}
__device__ __forceinline__ float scan_up(float x, int t) {
    const unsigned FM = 0xffffffffu; float o;
    o=__shfl_up_sync(FM,x,1);  if(t>=1)  x=fminf(x,o);
    o=__shfl_up_sync(FM,x,2);  if(t>=2)  x=fminf(x,o);
    o=__shfl_up_sync(FM,x,4);  if(t>=4)  x=fminf(x,o);
    o=__shfl_up_sync(FM,x,8);  if(t>=8)  x=fminf(x,o);
    o=__shfl_up_sync(FM,x,16); if(t>=16) x=fminf(x,o);
    return x;
}
__device__ __forceinline__ float scan_dn(float x, int t) {
    const unsigned FM = 0xffffffffu; float o;
    o=__shfl_down_sync(FM,x,1);  if(t<=30) x=fminf(x,o);
    o=__shfl_down_sync(FM,x,2);  if(t<=29) x=fminf(x,o);
    o=__shfl_down_sync(FM,x,4);  if(t<=27) x=fminf(x,o);
    o=__shfl_down_sync(FM,x,8);  if(t<=23) x=fminf(x,o);
    o=__shfl_down_sync(FM,x,16); if(t<=15) x=fminf(x,o);
    return x;
}
__device__ __forceinline__ unsigned seed_bits(int img, int r, int t) {
    return (g_seed[img*H*16 + r*16 + (t>>1)] >> ((t&1)*16)) & 0xffffu;
}
// original single-row forward step (validated in R5): p -> new row
__device__ __forceinline__ void row_step_fwd(float* p, unsigned hw, const float* aj, int t) {
    const unsigned FM = 0xffffffffu;
    float pvL=__shfl_up_sync(FM,p[15],1);  if(t==0)  pvL=CINF;
    float pvR=__shfl_down_sync(FM,p[0],1); if(t==31) pvR=CINF;
    float v[16];
    #pragma unroll
    for (int c=0;c<16;c++) {
        float pl=(c==0)?pvL:p[c-1], pr=(c==15)?pvR:p[c+1];
        float dv=((hw>>c)&1u)?0.0f:CINF;
        v[c]=fminf(fminf(dv,p[c]+CA),fminf(pl,pr)+CB)-aj[c];
    }
    #pragma unroll
    for (int c=1;c<16;c++) v[c]=fminf(v[c-1],v[c]);
    float s=scan_up(v[15],t);
    float excl=__shfl_up_sync(FM,s,1); if(t==0) excl=BIG;
    #pragma unroll
    for (int c=0;c<16;c++) p[c]=aj[c]+fminf(excl,v[c]);
}
// original single-row backward step
__device__ __forceinline__ void row_step_bwd(float* p, const float* drw, const float* ar, int t) {
    const unsigned FM = 0xffffffffu;
    float pvL=__shfl_up_sync(FM,p[15],1);  if(t==0)  pvL=CINF;
    float pvR=__shfl_down_sync(FM,p[0],1); if(t==31) pvR=CINF;
    float v[16];
    #pragma unroll
    for (int c=0;c<16;c++) {
        float pl=(c==0)?pvL:p[c-1], pr=(c==15)?pvR:p[c+1];
        v[c]=fminf(fminf(drw[c],p[c]+CA),fminf(pl,pr)+CB)-ar[c];
    }
    #pragma unroll
    for (int c=14;c>=0;c--) v[c]=fminf(v[c],v[c+1]);
    float s=scan_dn(v[0],t);
    float excl=__shfl_down_sync(FM,s,1); if(t==31) excl=BIG;
    #pragma unroll
    for (int c=0;c<16;c++) p[c]=ar[c]+fminf(excl,v[c]);
}
// one 3-point cone aging step
__device__ __forceinline__ void age_step(float* x, int t) {
    const unsigned FM = 0xffffffffu;
    float xl=__shfl_up_sync(FM,x[15],1);  if(t==0)  xl=CINF;
    float xr=__shfl_down_sync(FM,x[0],1); if(t==31) xr=CINF;
    float y[16];
    #pragma unroll
    for (int c=0;c<16;c++) {
        float l=(c==0)?xl:x[c-1], r=(c==15)?xr:x[c+1];
        y[c]=fminf(x[c]+CA,fminf(l,r)+CB);
    }
    #pragma unroll
    for (int c=0;c<16;c++) x[c]=y[c];
}
// composed serial step core: band-17 over pe + L, then cummin (dir: 0=fwd,1=bwd)
__device__ __forceinline__ void composed_step(float* p, const float* Lc, const float* W8C,
                                              const float* ax, int t, int dir) {
    const unsigned FM = 0xffffffffu;
    float pe[32];
    #pragma unroll
    for (int k=0;k<8;k++) { float h=__shfl_up_sync(FM,p[8+k],1); pe[k]=(t==0)?CINF:h; }
    #pragma unroll
    for (int c=0;c<16;c++) pe[8+c]=p[c];
    #pragma unroll
    for (int k=0;k<8;k++) { float h=__shfl_down_sync(FM,p[k],1); pe[24+k]=(t==31)?CINF:h; }
    float v[16];
    #pragma unroll
    for (int c=0;c<16;c++) {
        float m=Lc[c];
        #pragma unroll
        for (int o=-8;o<=8;o++) m=fminf(m, pe[c+8+o]+W8C[o<0?-o:o]);
        v[c]=m-ax[c];
    }
    if (dir==0) {
        #pragma unroll
        for (int c=1;c<16;c++) v[c]=fminf(v[c-1],v[c]);
        float s=scan_up(v[15],t);
        float excl=__shfl_up_sync(FM,s,1); if(t==0) excl=BIG;
        #pragma unroll
        for (int c=0;c<16;c++) p[c]=ax[c]+fminf(excl,v[c]);
    } else {
        #pragma unroll
        for (int c=14;c>=0;c--) v[c]=fminf(v[c],v[c+1]);
        float s=scan_dn(v[0],t);
        float excl=__shfl_down_sync(FM,s,1); if(t==31) excl=BIG;
        #pragma unroll
        for (int c=0;c<16;c++) p[c]=ax[c]+fminf(excl,v[c]);
    }
}

// ---------------- seed kernel (validated R7) ----------------
__global__ __launch_bounds__(128) void seed_kernel(const int* __restrict__ target) {
    __shared__ unsigned mbits[H*18];
    __shared__ int sflag[2];
    const int img=blockIdx.x;
    const int* tg=target+img*NPIX;
    unsigned* sb=g_seed+img*H*16;
    const int tid=threadIdx.x, lane=tid&31, sl=tid&7, sg=tid>>3, col0=tid*4;
    const unsigned FM=0xffffffffu;

    if (tid<2) sflag[tid]=0;
    if (tid==0) g_mxi[img]=0;
    for (int r=tid;r<H;r+=128) { mbits[r*18+0]=0u; mbits[r*18+17]=0u; }
    __syncthreads();

    bool any1=false, any0=false;
    for (int r=0;r<H;r++) {
        int4 tv=*(const int4*)(tg+r*W+col0);
        unsigned nib=(unsigned)(tv.x!=0)|((unsigned)(tv.y!=0)<<1)
                    |((unsigned)(tv.z!=0)<<2)|((unsigned)(tv.w!=0)<<3);
        any1|=(nib!=0u); any0|=(nib!=15u);
        unsigned word=nib<<(4*sl);
        word|=__shfl_xor_sync(FM,word,1);
        word|=__shfl_xor_sync(FM,word,2);
        word|=__shfl_xor_sync(FM,word,4);
        if (sl==0) mbits[r*18+1+sg]=word;
    }
    if (__any_sync(FM,any1)&&lane==0) atomicOr(&sflag[0],1);
    if (__any_sync(FM,any0)&&lane==0) atomicOr(&sflag[1],1);
    __syncthreads();
    const int hasb=sflag[0]&sflag[1];

    for (int idx=tid;idx<H*16;idx+=128) {
        int r=idx>>4, w=idx&15;
        unsigned swd;
        if (hasb) {
            unsigned dil=0u, ero=0xffffffffu;
            #pragma unroll
            for (int dr=-1;dr<=1;dr++) {
                int r2=r+dr;
                if (r2<0||r2>=H) continue;
                unsigned M=mbits[r2*18+1+w], Ml=mbits[r2*18+w], Mr=mbits[r2*18+2+w];
                unsigned Mlg=(w==0)?0xffffffffu:Ml, Mrg=(w==15)?0xffffffffu:Mr;
                dil|=M|__funnelshift_l(Ml,M,1)|__funnelshift_r(M,Mr,1);
                ero&=M&__funnelshift_l(Mlg,M,1)&__funnelshift_r(M,Mrg,1);
            }
            swd=dil&~ero;
        } else swd=~mbits[r*18+1+w];
        sb[idx]=swd;
    }
    if (tid==0) g_flags[img]=sflag[0]|(sflag[1]<<1);
}

// ---------------- L precompute, forward (sources = seed rows) ----------------
__global__ __launch_bounds__(32) void Lfwd_kernel() {
    const int g=blockIdx.x, img=blockIdx.y, t=threadIdx.x, c0=t*16;
    float x[16];
    unsigned hw=seed_bits(img,8*g,t);
    #pragma unroll
    for (int c=0;c<16;c++) x[c]=((hw>>c)&1u)?0.0f:CINF;
    for (int k=1;k<8;k++) {
        age_step(x,t);
        unsigned h2=seed_bits(img,8*g+k,t);
        #pragma unroll
        for (int c=0;c<16;c++) x[c]=fminf(x[c],((h2>>c)&1u)?0.0f:CINF);
    }
    st16(g_L+(img*NG+g)*W+c0,x);
}

// ---------------- L precompute, backward (sources = forward rows, proc order) ----------------
__global__ __launch_bounds__(32) void Lbwd_kernel() {
    const int g=blockIdx.x, img=blockIdx.y, t=threadIdx.x, c0=t*16;
    const float* dd=g_dist+img*NPIX;
    float x[16], s2[16];
    ld16(dd+(511-8*g)*W+c0,x);
    for (int k=1;k<8;k++) {
        age_step(x,t);
        ld16(dd+(511-(8*g+k))*W+c0,s2);
        #pragma unroll
        for (int c=0;c<16;c++) x[c]=fminf(x[c],s2[c]);
    }
    st16(g_L+(img*NG+g)*W+c0,x);
}

#define W8_(u) ((float)(CB*(double)(u)+CA*(double)(8-(u))))

// ---------------- serial forward: 64 composed steps ----------------
__global__ __launch_bounds__(32) void serial_fwd_kernel() {
    const int img=blockIdx.x, t=threadIdx.x, c0=t*16;
    float* dd=g_dist+img*NPIX;
    const float* Lb=g_L+img*NG*W;
    const float W8C[9]={W8_(0),W8_(1),W8_(2),W8_(3),W8_(4),W8_(5),W8_(6),W8_(7),W8_(8)};
    float aj[16];
    #pragma unroll
    for (int c=0;c<16;c++) aj[c]=CA*(float)(c0+c);
    float p[16];
    #pragma unroll
    for (int c=0;c<16;c++) p[c]=CINF;
    float Lc[16]; ld16(Lb+c0,Lc);
    for (int g=0;g<NG;g++) {
        float Ln[16];
        if (g<NG-1) ld16(Lb+(g+1)*W+c0,Ln);
        composed_step(p,Lc,W8C,aj,t,0);
        st16(dd+(8*g+7)*W+c0,p);
        #pragma unroll
        for (int c=0;c<16;c++) Lc[c]=Ln[c];
    }
}

// ---------------- fill forward: rows 8g..8g+6 ----------------
__global__ __launch_bounds__(32) void fill_fwd_kernel() {
    const int g=blockIdx.x, img=blockIdx.y, t=threadIdx.x, c0=t*16;
    float* dd=g_dist+img*NPIX;
    float aj[16];
    #pragma unroll
    for (int c=0;c<16;c++) aj[c]=CA*(float)(c0+c);
    float p[16];
    if (g==0) { 
        #pragma unroll
        for (int c=0;c<16;c++) p[c]=CINF;
    } else ld16(dd+(8*g-1)*W+c0,p);
    for (int k=0;k<7;k++) {
        row_step_fwd(p,seed_bits(img,8*g+k,t),aj,t);
        st16(dd+(8*g+k)*W+c0,p);
    }
}

// ---------------- serial backward: 64 composed steps over reversed rows ----------------
__global__ __launch_bounds__(32) void serial_bwd_kernel() {
    const int img=blockIdx.x, t=threadIdx.x, c0=t*16;
    const unsigned FM=0xffffffffu;
    float* dd=g_dist+img*NPIX;
    const float* Lb=g_L+img*NG*W;
    const float W8C[9]={W8_(0),W8_(1),W8_(2),W8_(3),W8_(4),W8_(5),W8_(6),W8_(7),W8_(8)};
    float ar[16];
    #pragma unroll
    for (int c=0;c<16;c++) ar[c]=CA*(float)(W-1-(c0+c));
    float p[16];
    #pragma unroll
    for (int c=0;c<16;c++) p[c]=CINF;
    float lmax=0.0f;
    float Lc[16]; ld16(Lb+c0,Lc);
    for (int g=0;g<NG;g++) {
        float Ln[16];
        if (g<NG-1) ld16(Lb+(g+1)*W+c0,Ln);
        composed_step(p,Lc,W8C,ar,t,1);
        #pragma unroll
        for (int c=0;c<16;c++) lmax=fmaxf(lmax,p[c]);
        st16(dd+(511-(8*g+7))*W+c0,p);
        #pragma unroll
        for (int c=0;c<16;c++) Lc[c]=Ln[c];
    }
    #pragma unroll
    for (int d=16;d>0;d>>=1) lmax=fmaxf(lmax,__shfl_xor_sync(FM,lmax,d));
    if (t==0) atomicMax(&g_mxi[img],__float_as_int(lmax));
}

// ---------------- fill backward: proc rows 8g..8g+6 ----------------
__global__ __launch_bounds__(32) void fill_bwd_kernel() {
    const int g=blockIdx.x, img=blockIdx.y, t=threadIdx.x, c0=t*16;
    const unsigned FM=0xffffffffu;
    float* dd=g_dist+img*NPIX;
    float ar[16];
    #pragma unroll
    for (int c=0;c<16;c++) ar[c]=CA*(float)(W-1-(c0+c));
    float p[16];
    if (g==0) { 
        #pragma unroll
        for (int c=0;c<16;c++) p[c]=CINF;
    } else ld16(dd+(512-8*g)*W+c0,p);   // serial output at proc row 8g-1
    float lmax=0.0f;
    for (int k=0;k<7;k++) {
        float drw[16];
        ld16(dd+(511-(8*g+k))*W+c0,drw);      // forward value at this row
        row_step_bwd(p,drw,ar,t);
        #pragma unroll
        for (int c=0;c<16;c++) lmax=fmaxf(lmax,p[c]);
        st16(dd+(511-(8*g+k))*W+c0,p);
    }
    #pragma unroll
    for (int d=16;d>0;d>>=1) lmax=fmaxf(lmax,__shfl_xor_sync(FM,lmax,d));
    if (t==0) atomicMax(&g_mxi[img],__float_as_int(lmax));
}

// ---------------- loss partial sums (validated) ----------------
__global__ __launch_bounds__(LBLK) void loss_partial(const float* __restrict__ pred,
                                                     const int* __restrict__ target) {
    const int img=blockIdx.x/BPI, sub=blockIdx.x%BPI, base=img*NPIX;
    const float mx=__int_as_float(g_mxi[img]);
    const int hfg=g_flags[img]&1;
    const float inv=1.0f/fmaxf(mx,1e-12f);
    const int usediv=(mx>0.0f)?1:0;

    float sF=0.f,sB=0.f,sP=0.f,sT=0.f,sPT=0.f;
    for (int idx=sub*LBLK+threadIdx.x; idx<NPIX; idx+=BPI*LBLK) {
        float x=pred[base+idx];
        int tv=target[base+idx];
        float d=g_dist[base+idx];
        float p=1.0f/(1.0f+expf(-x));
        float ax=fabsf(x);
        float bce=log1pf(expf(-ax))+(tv?fmaxf(-x,0.0f):fmaxf(x,0.0f));
        float pt=tv?p:(1.0f-p);
        float omp=1.0f-pt;
        float alpha=tv?0.25f:0.75f;
        sF+=alpha*omp*omp*bce;
        float dn=hfg?(usediv?d*inv:d):1.0f;
        sB+=omp*(1.0f+dn);
        sP+=p;
        if (tv) { sT+=1.0f; sPT+=p; }
    }
    float vals[5]={sF,sB,sP,sT,sPT};
    #pragma unroll
    for (int k=0;k<5;k++) {
        float v=vals[k];
        #pragma unroll
        for (int d=16;d>0;d>>=1) v+=__shfl_xor_sync(0xffffffffu,v,d);
        vals[k]=v;
    }
    __shared__ float s5[LBLK/32][5];
    int lane=threadIdx.x&31, wid=threadIdx.x>>5;
    if (lane==0) { 
        #pragma unroll
        for (int k=0;k<5;k++) s5[wid][k]=vals[k];
    }
    __syncthreads();
    if (threadIdx.x==0) {
        #pragma unroll
        for (int k=0;k<5;k++) {
            float a=0.f;
            for (int w=0;w<LBLK/32;w++) a+=s5[w][k];
            g_part[blockIdx.x*5+k]=a;
        }
    }
}

// ---------------- final combine (validated) ----------------
__global__ void loss_final(const float* __restrict__ lv, float* __restrict__ out,
                           int out_size) {
    __shared__ double sd[BATCH][4];
    int t=threadIdx.x;
    if (t<BATCH) {
        double F=0,Bd=0,P=0,T=0,PT=0;
        for (int b=0;b<BPI;b++) {
            const float* pp=g_part+(t*BPI+b)*5;
            F+=pp[0]; Bd+=pp[1]; P+=pp[2]; T+=pp[3]; PT+=pp[4];
        }
        double total=P+T, uni=total-PT;
        sd[t][0]=F; sd[t][1]=Bd;
        sd[t][2]=(2.0*PT+1e-6)/(total+1e-6);
        sd[t][3]=(PT+1e-6)/(uni+1e-6);
    }
    __syncthreads();
    if (t==0) {
        double F=0,Bd=0,D=0,I=0;
        for (int b=0;b<BATCH;b++) { F+=sd[b][0]; Bd+=sd[b][1]; D+=sd[b][2]; I+=sd[b][3]; }
        double N=(double)BATCH*(double)NPIX;
        double focal=F/N, bnd=Bd/N;
        double dice=1.0-D/(double)BATCH, iou=1.0-I/(double)BATCH;
        double l0=lv[0],l1=lv[1],l2=lv[2],l3=lv[3];
        double tot=exp(-l0)*focal+l0+exp(-l1)*dice+l1+exp(-l2)*bnd+l2+exp(-l3)*iou+l3;
        if (out_size>0) out[0]=(float)tot;
        if (out_size>1) out[1]=(float)focal;
        if (out_size>2) out[2]=(float)dice;
        if (out_size>3) out[3]=(float)bnd;
        if (out_size>4) out[4]=(float)iou;
    }
}

extern "C" void kernel_launch(void* const* d_in, const int* in_sizes, int n_in,
                              void* d_out, int out_size) {
    const float* pred   = (const float*)d_in[0];
    const int*   target = (const int*)d_in[1];
    const float* lv     = (const float*)d_in[2];
    float* out = (float*)d_out;

    dim3 gg(NG, BATCH);
    seed_kernel<<<BATCH, 128>>>(target);
    Lfwd_kernel<<<gg, 32>>>();
    serial_fwd_kernel<<<BATCH, 32>>>();
    fill_fwd_kernel<<<gg, 32>>>();
    Lbwd_kernel<<<gg, 32>>>();
    serial_bwd_kernel<<<BATCH, 32>>>();
    fill_bwd_kernel<<<gg, 32>>>();
    loss_partial<<<NLB, LBLK>>>(pred, target);
    loss_final<<<1, 32>>>(lv, out, out_size);
}

// round 12
// speedup vs baseline: 2.9304x; 1.1402x over previous
#include <cuda_runtime.h>
#include <math.h>

#define H 512
#define W 512
#define BATCH 16
#define NPIX (H*W)
#define CA 0.955f
#define CB 1.3693f
#define CINF 1e6f
#define BIG 1e30f
#define NG 32                 // 32 groups of 16 rows
#define RR 16
#define LBLK 256
#define BPI 32
#define NLB (BATCH*BPI)

#define SD  ((float)((double)CB-(double)CA))        // slope
#define S16 ((float)(16.0*((double)CB-(double)CA))) // 16*s
#define C16A ((float)(16.0*(double)CA))

__device__ float    g_dist[BATCH*NPIX];
__device__ int      g_mxi[BATCH];
__device__ int      g_flags[BATCH];
__device__ float    g_part[NLB*5];
__device__ unsigned g_seed[BATCH*H*16];
__device__ float    g_L[BATCH*NG*W];

__device__ __forceinline__ void ld16(const float* b, float* a) {
    float4 x0=*(const float4*)(b+0), x1=*(const float4*)(b+4);
    float4 x2=*(const float4*)(b+8), x3=*(const float4*)(b+12);
    a[0]=x0.x;a[1]=x0.y;a[2]=x0.z;a[3]=x0.w; a[4]=x1.x;a[5]=x1.y;a[6]=x1.z;a[7]=x1.w;
    a[8]=x2.x;a[9]=x2.y;a[10]=x2.z;a[11]=x2.w; a[12]=x3.x;a[13]=x3.y;a[14]=x3.z;a[15]=x3.w;
}
__device__ __forceinline__ void st16(float* b, const float* a) {
    *(float4*)(b+0)=make_float4(a[0],a[1],a[2],a[3]);
    *(float4*)(b+4)=make_float4(a[4],a[5],a[6],a[7]);
    *(float4*)(b+8)=make_float4(a[8],a[9],a[10],a[11]);
    *(float4*)(b+12)=make_float4(a[12],a[13],a[14],a[15]);
}
__device__ __forceinline__ float scan_up(float x, int t) {
    const unsigned FM=0xffffffffu; float o;
    o=__shfl_up_sync(FM,x,1);  if(t>=1)  x=fminf(x,o);
    o=__shfl_up_sync(FM,x,2);  if(t>=2)  x=fminf(x,o);
    o=__shfl_up_sync(FM,x,4);  if(t>=4)  x=fminf(x,o);
    o=__shfl_up_sync(FM,x,8);  if(t>=8)  x=fminf(x,o);
    o=__shfl_up_sync(FM,x,16); if(t>=16) x=fminf(x,o);
    return x;
}
__device__ __forceinline__ float scan_dn(float x, int t) {
    const unsigned FM=0xffffffffu; float o;
    o=__shfl_down_sync(FM,x,1);  if(t<=30) x=fminf(x,o);
    o=__shfl_down_sync(FM,x,2);  if(t<=29) x=fminf(x,o);
    o=__shfl_down_sync(FM,x,4);  if(t<=27) x=fminf(x,o);
    o=__shfl_down_sync(FM,x,8);  if(t<=23) x=fminf(x,o);
    o=__shfl_down_sync(FM,x,16); if(t<=15) x=fminf(x,o);
    return x;
}
__device__ __forceinline__ unsigned seed_bits(int img, int r, int t) {
    return (g_seed[img*H*16 + r*16 + (t>>1)] >> ((t&1)*16)) & 0xffffu;
}
__device__ __forceinline__ void row_step_fwd(float* p, unsigned hw, const float* aj, int t) {
    const unsigned FM=0xffffffffu;
    float pvL=__shfl_up_sync(FM,p[15],1);  if(t==0)  pvL=CINF;
    float pvR=__shfl_down_sync(FM,p[0],1); if(t==31) pvR=CINF;
    float v[16];
    #pragma unroll
    for (int c=0;c<16;c++) {
        float pl=(c==0)?pvL:p[c-1], pr=(c==15)?pvR:p[c+1];
        float dv=((hw>>c)&1u)?0.0f:CINF;
        v[c]=fminf(fminf(dv,p[c]+CA),fminf(pl,pr)+CB)-aj[c];
    }
    #pragma unroll
    for (int c=1;c<16;c++) v[c]=fminf(v[c-1],v[c]);
    float s=scan_up(v[15],t);
    float excl=__shfl_up_sync(FM,s,1); if(t==0) excl=BIG;
    #pragma unroll
    for (int c=0;c<16;c++) p[c]=aj[c]+fminf(excl,v[c]);
}
__device__ __forceinline__ void row_step_bwd(float* p, const float* drw, const float* ar, int t) {
    const unsigned FM=0xffffffffu;
    float pvL=__shfl_up_sync(FM,p[15],1);  if(t==0)  pvL=CINF;
    float pvR=__shfl_down_sync(FM,p[0],1); if(t==31) pvR=CINF;
    float v[16];
    #pragma unroll
    for (int c=0;c<16;c++) {
        float pl=(c==0)?pvL:p[c-1], pr=(c==15)?pvR:p[c+1];
        v[c]=fminf(fminf(drw[c],p[c]+CA),fminf(pl,pr)+CB)-ar[c];
    }
    #pragma unroll
    for (int c=14;c>=0;c--) v[c]=fminf(v[c],v[c+1]);
    float s=scan_dn(v[0],t);
    float excl=__shfl_down_sync(FM,s,1); if(t==31) excl=BIG;
    #pragma unroll
    for (int c=0;c<16;c++) p[c]=ar[c]+fminf(excl,v[c]);
}
__device__ __forceinline__ void age_step(float* x, int t) {
    const unsigned FM=0xffffffffu;
    float xl=__shfl_up_sync(FM,x[15],1);  if(t==0)  xl=CINF;
    float xr=__shfl_down_sync(FM,x[0],1); if(t==31) xr=CINF;
    float y[16];
    #pragma unroll
    for (int c=0;c<16;c++) {
        float l=(c==0)?xl:x[c-1], r=(c==15)?xr:x[c+1];
        y[c]=fminf(x[c]+CA,fminf(l,r)+CB);
    }
    #pragma unroll
    for (int c=0;c<16;c++) x[c]=y[c];
}
// composed 16-row step: band via slope doubling, then cummin. dir 0=fwd,1=bwd
__device__ __forceinline__ void composed_step16(float* p, const float* Lc,
                                                const float* ax, int t, int dir) {
    const unsigned FM=0xffffffffu;
    float pe[48];           // cols c0-16 .. c0+31
    #pragma unroll
    for (int k=0;k<16;k++) { float h=__shfl_up_sync(FM,p[k],1); pe[k]=(t==0)?CINF:h; }
    #pragma unroll
    for (int c=0;c<16;c++) pe[16+c]=p[c];
    #pragma unroll
    for (int k=0;k<16;k++) { float h=__shfl_down_sync(FM,p[k],1); pe[32+k]=(t==31)?CINF:h; }
    // u=16 taps from original pe
    float TL[16], TR[16];
    #pragma unroll
    for (int c=0;c<16;c++) { TL[c]=pe[c]+S16; TR[c]=pe[32+c]+S16; }
    // left slope scan on copy A (descending, in place)
    float A[48];
    #pragma unroll
    for (int i=0;i<48;i++) A[i]=pe[i];
    #pragma unroll
    for (int i=31;i>=2;i--)  A[i]=fminf(A[i],A[i-1]+SD);
    #pragma unroll
    for (int i=31;i>=4;i--)  A[i]=fminf(A[i],A[i-2]+(2.0f*SD));
    #pragma unroll
    for (int i=31;i>=8;i--)  A[i]=fminf(A[i],A[i-4]+(4.0f*SD));
    #pragma unroll
    for (int i=31;i>=16;i--) A[i]=fminf(A[i],A[i-8]+(8.0f*SD));
    // right slope scan on pe (ascending, in place)
    #pragma unroll
    for (int i=16;i<=45;i++) pe[i]=fminf(pe[i],pe[i+1]+SD);
    #pragma unroll
    for (int i=16;i<=43;i++) pe[i]=fminf(pe[i],pe[i+2]+(2.0f*SD));
    #pragma unroll
    for (int i=16;i<=39;i++) pe[i]=fminf(pe[i],pe[i+4]+(4.0f*SD));
    #pragma unroll
    for (int i=16;i<=31;i++) pe[i]=fminf(pe[i],pe[i+8]+(8.0f*SD));
    float v[16];
    #pragma unroll
    for (int c=0;c<16;c++) {
        float b=fminf(fminf(A[16+c],TL[c]),fminf(pe[16+c],TR[c]));
        v[c]=fminf(Lc[c],b+C16A)-ax[c];
    }
    if (dir==0) {
        #pragma unroll
        for (int c=1;c<16;c++) v[c]=fminf(v[c-1],v[c]);
        float s=scan_up(v[15],t);
        float excl=__shfl_up_sync(FM,s,1); if(t==0) excl=BIG;
        #pragma unroll
        for (int c=0;c<16;c++) p[c]=ax[c]+fminf(excl,v[c]);
    } else {
        #pragma unroll
        for (int c=14;c>=0;c--) v[c]=fminf(v[c],v[c+1]);
        float s=scan_dn(v[0],t);
        float excl=__shfl_down_sync(FM,s,1); if(t==31) excl=BIG;
        #pragma unroll
        for (int c=0;c<16;c++) p[c]=ax[c]+fminf(excl,v[c]);
    }
}

__global__ __launch_bounds__(128) void seed_kernel(const int* __restrict__ target) {
    __shared__ unsigned mbits[H*18];
    __shared__ int sflag[2];
    const int img=blockIdx.x;
    const int* tg=target+img*NPIX;
    unsigned* sb=g_seed+img*H*16;
    const int tid=threadIdx.x, lane=tid&31, sl=tid&7, sg=tid>>3, col0=tid*4;
    const unsigned FM=0xffffffffu;
    if (tid<2) sflag[tid]=0;
    if (tid==0) g_mxi[img]=0;
    for (int r=tid;r<H;r+=128) { mbits[r*18+0]=0u; mbits[r*18+17]=0u; }
    __syncthreads();
    bool any1=false, any0=false;
    for (int r=0;r<H;r++) {
        int4 tv=*(const int4*)(tg+r*W+col0);
        unsigned nib=(unsigned)(tv.x!=0)|((unsigned)(tv.y!=0)<<1)
                    |((unsigned)(tv.z!=0)<<2)|((unsigned)(tv.w!=0)<<3);
        any1|=(nib!=0u); any0|=(nib!=15u);
        unsigned word=nib<<(4*sl);
        word|=__shfl_xor_sync(FM,word,1);
        word|=__shfl_xor_sync(FM,word,2);
        word|=__shfl_xor_sync(FM,word,4);
        if (sl==0) mbits[r*18+1+sg]=word;
    }
    if (__any_sync(FM,any1)&&lane==0) atomicOr(&sflag[0],1);
    if (__any_sync(FM,any0)&&lane==0) atomicOr(&sflag[1],1);
    __syncthreads();
    const int hasb=sflag[0]&sflag[1];
    for (int idx=tid;idx<H*16;idx+=128) {
        int r=idx>>4, w=idx&15;
        unsigned swd;
        if (hasb) {
            unsigned dil=0u, ero=0xffffffffu;
            #pragma unroll
            for (int dr=-1;dr<=1;dr++) {
                int r2=r+dr;
                if (r2<0||r2>=H) continue;
                unsigned M=mbits[r2*18+1+w], Ml=mbits[r2*18+w], Mr=mbits[r2*18+2+w];
                unsigned Mlg=(w==0)?0xffffffffu:Ml, Mrg=(w==15)?0xffffffffu:Mr;
                dil|=M|__funnelshift_l(Ml,M,1)|__funnelshift_r(M,Mr,1);
                ero&=M&__funnelshift_l(Mlg,M,1)&__funnelshift_r(M,Mrg,1);
            }
            swd=dil&~ero;
        } else swd=~mbits[r*18+1+w];
        sb[idx]=swd;
    }
    if (tid==0) g_flags[img]=sflag[0]|(sflag[1]<<1);
}

__global__ __launch_bounds__(32) void Lfwd_kernel() {
    const int g=blockIdx.x, img=blockIdx.y, t=threadIdx.x, c0=t*16;
    float x[16];
    unsigned hw=seed_bits(img,RR*g,t);
    #pragma unroll
    for (int c=0;c<16;c++) x[c]=((hw>>c)&1u)?0.0f:CINF;
    for (int k=1;k<RR;k++) {
        age_step(x,t);
        unsigned h2=seed_bits(img,RR*g+k,t);
        #pragma unroll
        for (int c=0;c<16;c++) x[c]=fminf(x[c],((h2>>c)&1u)?0.0f:CINF);
    }
    st16(g_L+(img*NG+g)*W+c0,x);
}

__global__ __launch_bounds__(32) void Lbwd_kernel() {
    const int g=blockIdx.x, img=blockIdx.y, t=threadIdx.x, c0=t*16;
    const float* dd=g_dist+img*NPIX;
    float x[16], s2[16];
    ld16(dd+(511-RR*g)*W+c0,x);
    for (int k=1;k<RR;k++) {
        age_step(x,t);
        ld16(dd+(511-(RR*g+k))*W+c0,s2);
        #pragma unroll
        for (int c=0;c<16;c++) x[c]=fminf(x[c],s2[c]);
    }
    st16(g_L+(img*NG+g)*W+c0,x);
}

__global__ __launch_bounds__(32) void serial_fwd_kernel() {
    const int img=blockIdx.x, t=threadIdx.x, c0=t*16;
    float* dd=g_dist+img*NPIX;
    const float* Lb=g_L+img*NG*W;
    float aj[16];
    #pragma unroll
    for (int c=0;c<16;c++) aj[c]=CA*(float)(c0+c);
    float p[16];
    #pragma unroll
    for (int c=0;c<16;c++) p[c]=CINF;
    float Lc[16]; ld16(Lb+c0,Lc);
    for (int g=0;g<NG;g++) {
        float Ln[16];
        if (g<NG-1) ld16(Lb+(g+1)*W+c0,Ln);
        composed_step16(p,Lc,aj,t,0);
        st16(dd+(RR*g+RR-1)*W+c0,p);
        #pragma unroll
        for (int c=0;c<16;c++) Lc[c]=Ln[c];
    }
}

__global__ __launch_bounds__(32) void fill_fwd_kernel() {
    const int g=blockIdx.x, img=blockIdx.y, t=threadIdx.x, c0=t*16;
    float* dd=g_dist+img*NPIX;
    float aj[16];
    #pragma unroll
    for (int c=0;c<16;c++) aj[c]=CA*(float)(c0+c);
    float p[16];
    if (g==0) {
        #pragma unroll
        for (int c=0;c<16;c++) p[c]=CINF;
    } else ld16(dd+(RR*g-1)*W+c0,p);
    for (int k=0;k<RR-1;k++) {
        row_step_fwd(p,seed_bits(img,RR*g+k,t),aj,t);
        st16(dd+(RR*g+k)*W+c0,p);
    }
}

__global__ __launch_bounds__(32) void serial_bwd_kernel() {
    const int img=blockIdx.x, t=threadIdx.x, c0=t*16;
    const unsigned FM=0xffffffffu;
    float* dd=g_dist+img*NPIX;
    const float* Lb=g_L+img*NG*W;
    float ar[16];
    #pragma unroll
    for (int c=0;c<16;c++) ar[c]=CA*(float)(W-1-(c0+c));
    float p[16];
    #pragma unroll
    for (int c=0;c<16;c++) p[c]=CINF;
    float lmax=0.0f;
    float Lc[16]; ld16(Lb+c0,Lc);
    for (int g=0;g<NG;g++) {
        float Ln[16];
        if (g<NG-1) ld16(Lb+(g+1)*W+c0,Ln);
        composed_step16(p,Lc,ar,t,1);
        #pragma unroll
        for (int c=0;c<16;c++) lmax=fmaxf(lmax,p[c]);
        st16(dd+(511-(RR*g+RR-1))*W+c0,p);
        #pragma unroll
        for (int c=0;c<16;c++) Lc[c]=Ln[c];
    }
    #pragma unroll
    for (int d=16;d>0;d>>=1) lmax=fmaxf(lmax,__shfl_xor_sync(FM,lmax,d));
    if (t==0) atomicMax(&g_mxi[img],__float_as_int(lmax));
}

__global__ __launch_bounds__(32) void fill_bwd_kernel() {
    const int g=blockIdx.x, img=blockIdx.y, t=threadIdx.x, c0=t*16;
    const unsigned FM=0xffffffffu;
    float* dd=g_dist+img*NPIX;
    float ar[16];
    #pragma unroll
    for (int c=0;c<16;c++) ar[c]=CA*(float)(W-1-(c0+c));
    float p[16];
    if (g==0) {
        #pragma unroll
        for (int c=0;c<16;c++) p[c]=CINF;
    } else ld16(dd+(512-RR*g)*W+c0,p);   // serial output at proc row RR*g-1
    float lmax=0.0f;
    for (int k=0;k<RR-1;k++) {
        float drw[16];
        ld16(dd+(511-(RR*g+k))*W+c0,drw);
        row_step_bwd(p,drw,ar,t);
        #pragma unroll
        for (int c=0;c<16;c++) lmax=fmaxf(lmax,p[c]);
        st16(dd+(511-(RR*g+k))*W+c0,p);
    }
    #pragma unroll
    for (int d=16;d>0;d>>=1) lmax=fmaxf(lmax,__shfl_xor_sync(FM,lmax,d));
    if (t==0) atomicMax(&g_mxi[img],__float_as_int(lmax));
}

__global__ __launch_bounds__(LBLK) void loss_partial(const float* __restrict__ pred,
                                                     const int* __restrict__ target) {
    const int img=blockIdx.x/BPI, sub=blockIdx.x%BPI, base=img*NPIX;
    const float mx=__int_as_float(g_mxi[img]);
    const int hfg=g_flags[img]&1;
    const float inv=1.0f/fmaxf(mx,1e-12f);
    const int usediv=(mx>0.0f)?1:0;
    float sF=0.f,sB=0.f,sP=0.f,sT=0.f,sPT=0.f;
    for (int idx=sub*LBLK+threadIdx.x; idx<NPIX; idx+=BPI*LBLK) {
        float x=pred[base+idx];
        int tv=target[base+idx];
        float d=g_dist[base+idx];
        float p=1.0f/(1.0f+expf(-x));
        float ax=fabsf(x);
        float bce=log1pf(expf(-ax))+(tv?fmaxf(-x,0.0f):fmaxf(x,0.0f));
        float pt=tv?p:(1.0f-p);
        float omp=1.0f-pt;
        float alpha=tv?0.25f:0.75f;
        sF+=alpha*omp*omp*bce;
        float dn=hfg?(usediv?d*inv:d):1.0f;
        sB+=omp*(1.0f+dn);
        sP+=p;
        if (tv) { sT+=1.0f; sPT+=p; }
    }
    float vals[5]={sF,sB,sP,sT,sPT};
    #pragma unroll
    for (int k=0;k<5;k++) {
        float v=vals[k];
        #pragma unroll
        for (int d=16;d>0;d>>=1) v+=__shfl_xor_sync(0xffffffffu,v,d);
        vals[k]=v;
    }
    __shared__ float s5[LBLK/32][5];
    int lane=threadIdx.x&31, wid=threadIdx.x>>5;
    if (lane==0) {
        #pragma unroll
        for (int k=0;k<5;k++) s5[wid][k]=vals[k];
    }
    __syncthreads();
    if (threadIdx.x==0) {
        #pragma unroll
        for (int k=0;k<5;k++) {
            float a=0.f;
            for (int w=0;w<LBLK/32;w++) a+=s5[w][k];
            g_part[blockIdx.x*5+k]=a;
        }
    }
}

__global__ void loss_final(const float* __restrict__ lv, float* __restrict__ out,
                           int out_size) {
    __shared__ double sd[BATCH][4];
    int t=threadIdx.x;
    if (t<BATCH) {
        double F=0,Bd=0,P=0,T=0,PT=0;
        for (int b=0;b<BPI;b++) {
            const float* pp=g_part+(t*BPI+b)*5;
            F+=pp[0]; Bd+=pp[1]; P+=pp[2]; T+=pp[3]; PT+=pp[4];
        }
        double total=P+T, uni=total-PT;
        sd[t][0]=F; sd[t][1]=Bd;
        sd[t][2]=(2.0*PT+1e-6)/(total+1e-6);
        sd[t][3]=(PT+1e-6)/(uni+1e-6);
    }
    __syncthreads();
    if (t==0) {
        double F=0,Bd=0,D=0,I=0;
        for (int b=0;b<BATCH;b++) { F+=sd[b][0]; Bd+=sd[b][1]; D+=sd[b][2]; I+=sd[b][3]; }
        double N=(double)BATCH*(double)NPIX;
        double focal=F/N, bnd=Bd/N;
        double dice=1.0-D/(double)BATCH, iou=1.0-I/(double)BATCH;
        double l0=lv[0],l1=lv[1],l2=lv[2],l3=lv[3];
        double tot=exp(-l0)*focal+l0+exp(-l1)*dice+l1+exp(-l2)*bnd+l2+exp(-l3)*iou+l3;
        if (out_size>0) out[0]=(float)tot;
        if (out_size>1) out[1]=(float)focal;
        if (out_size>2) out[2]=(float)dice;
        if (out_size>3) out[3]=(float)bnd;
        if (out_size>4) out[4]=(float)iou;
    }
}

extern "C" void kernel_launch(void* const* d_in, const int* in_sizes, int n_in,
                              void* d_out, int out_size) {
    const float* pred   = (const float*)d_in[0];
    const int*   target = (const int*)d_in[1];
    const float* lv     = (const float*)d_in[2];
    float* out = (float*)d_out;

    dim3 gg(NG, BATCH);
    seed_kernel<<<BATCH, 128>>>(target);
    Lfwd_kernel<<<gg, 32>>>();
    serial_fwd_kernel<<<BATCH, 32>>>();
    fill_fwd_kernel<<<gg, 32>>>();
    Lbwd_kernel<<<gg, 32>>>();
    serial_bwd_kernel<<<BATCH, 32>>>();
    fill_bwd_kernel<<<gg, 32>>>();
    loss_partial<<<NLB, LBLK>>>(pred, target);
    loss_final<<<1, 32>>>(lv, out, out_size);
}